// round 1
// baseline (speedup 1.0000x reference)
#include <cuda_runtime.h>

// FastPooling "social" pooling, restructured:
//   H[j][cc][o] = sum_h hidden[j][h] * W[h*16+cc][o]        (dense GEMM, fp32)
//   out[i]      = relu(b + sum over winning fine cells c of H[winner(c)][coarse(c)])
// winner(c) = max j (last-write-wins in the reference's scatter); out-of-range
// peds "write zeros to cell 0" in the reference -> encode in_range bit so an
// out-of-range max-j suppresses cell 0's contribution.

#define N_MAX   512
#define HID     128
#define GRID_S  32
#define NCELLS  (GRID_S * GRID_S)   // 1024
#define CC_N    16                  // 4x4 coarse cells
#define OUTD    128

__device__ float g_H[N_MAX * CC_N * OUTD];   // 4 MB scratch

// ---------------------------------------------------------------------------
// K1: H = hidden (n x 128) @ Wperm (128 x 16*128), Wperm[k][cc*128+o] = W[(k*16+cc)*128+o]
// Tile: 64 rows x 128 cols per block; grid = (n/64, 16cc) = 128 blocks (one wave).
// ---------------------------------------------------------------------------
__global__ __launch_bounds__(256) void gemm1_kernel(
    const float* __restrict__ hidden,
    const float* __restrict__ W,
    int n)
{
    __shared__ float sh[64][HID];            // 32 KB hidden tile

    const int cc    = blockIdx.y;
    const int jbase = blockIdx.x * 64;
    const int t     = threadIdx.x;

    // load hidden tile (coalesced float4)
    const float4* hsrc = reinterpret_cast<const float4*>(hidden + (size_t)jbase * HID);
    float4*       hdst = reinterpret_cast<float4*>(&sh[0][0]);
    #pragma unroll
    for (int idx = t; idx < 64 * HID / 4; idx += 256) hdst[idx] = hsrc[idx];
    __syncthreads();

    const int colg = (t & 31) * 4;     // 4 contiguous output cols
    const int rowg = (t >> 5) * 8;     // 8 rows

    float acc[8][4];
    #pragma unroll
    for (int r = 0; r < 8; ++r)
        #pragma unroll
        for (int q = 0; q < 4; ++q) acc[r][q] = 0.f;

    #pragma unroll 4
    for (int k = 0; k < HID; ++k) {
        const float4 w = *reinterpret_cast<const float4*>(
            W + ((size_t)(k * CC_N + cc)) * OUTD + colg);
        #pragma unroll
        for (int r = 0; r < 8; ++r) {
            const float a = sh[rowg + r][k];   // warp-uniform broadcast LDS
            acc[r][0] += a * w.x;
            acc[r][1] += a * w.y;
            acc[r][2] += a * w.z;
            acc[r][3] += a * w.w;
        }
    }

    #pragma unroll
    for (int r = 0; r < 8; ++r) {
        const int j = jbase + rowg + r;
        if (j < n) {
            float4 v = make_float4(acc[r][0], acc[r][1], acc[r][2], acc[r][3]);
            *reinterpret_cast<float4*>(g_H + ((size_t)j * CC_N + cc) * OUTD + colg) = v;
        }
    }
}

// ---------------------------------------------------------------------------
// K2: per ped i — winner scatter (shared atomicMax), then gather-sum of H rows.
// ---------------------------------------------------------------------------
__global__ __launch_bounds__(256) void pool_gather_kernel(
    const float* __restrict__ obs2,
    const float* __restrict__ bias,
    float* __restrict__ out,
    int n)
{
    __shared__ int   win[NCELLS];     // encoded (j<<1)|in_range, -1 = empty
    __shared__ float red[8][OUTD];    // per-warp partial sums

    const int i = blockIdx.x;
    const int t = threadIdx.x;

    for (int c = t; c < NCELLS; c += 256) win[c] = -1;
    __syncthreads();

    const float xi = obs2[i * 2 + 0];
    const float yi = obs2[i * 2 + 1];

    // scatter: last-write-wins == max j; out-of-range j targets cell 0 with inr=0
    for (int j = t; j < n; j += 256) {
        if (j == i) continue;
        const float ox = (obs2[j * 2 + 0] - xi) * 4.0f + 16.0f;
        const float oy = (obs2[j * 2 + 1] - yi) * 4.0f + 16.0f;
        const bool inr = (ox >= 0.f) & (ox < 32.f) & (oy >= 0.f) & (oy < 32.f);
        int cell = 0;
        if (inr) cell = ((int)ox) * GRID_S + (int)oy;
        atomicMax(&win[cell], (j << 1) | (inr ? 1 : 0));
    }
    __syncthreads();

    // gather: each warp scans 128 fine cells; full 128-float row load per hit
    const int w    = t >> 5;
    const int lane = t & 31;
    float4 acc = make_float4(0.f, 0.f, 0.f, 0.f);

    const int cbase = w * 128;
    #pragma unroll 8
    for (int ci = 0; ci < 128; ++ci) {
        const int c   = cbase + ci;
        const int enc = win[c];                 // warp-uniform
        if (enc >= 0 && (enc & 1)) {            // valid in-range winner
            const int j  = enc >> 1;
            const int cc = (c >> 8) * 4 + ((c >> 3) & 3);
            const float4 v = *reinterpret_cast<const float4*>(
                g_H + ((size_t)j * CC_N + cc) * OUTD + lane * 4);
            acc.x += v.x; acc.y += v.y; acc.z += v.z; acc.w += v.w;
        }
    }

    *reinterpret_cast<float4*>(&red[w][lane * 4]) = acc;
    __syncthreads();

    if (t < OUTD) {
        float s = bias[t];
        #pragma unroll
        for (int r = 0; r < 8; ++r) s += red[r][t];
        out[(size_t)i * OUTD + t] = fmaxf(s, 0.f);
    }
}

// ---------------------------------------------------------------------------
// inputs (metadata order): hidden_state (n,128) f32 | obs1 (n,2) f32 (unused) |
//                          obs2 (n,2) f32 | W (2048,128) f32 | b (128,) f32
// output: (n,128) f32
// ---------------------------------------------------------------------------
extern "C" void kernel_launch(void* const* d_in, const int* in_sizes, int n_in,
                              void* d_out, int out_size)
{
    const float* hidden = (const float*)d_in[0];
    const float* obs2   = (const float*)d_in[2];
    const float* W      = (const float*)d_in[3];
    const float* bias   = (const float*)d_in[4];
    float*       out    = (float*)d_out;

    const int n = in_sizes[2] / 2;   // 512

    dim3 g1((n + 63) / 64, CC_N);
    gemm1_kernel<<<g1, 256>>>(hidden, W, n);
    pool_gather_kernel<<<n, 256>>>(obs2, bias, out, n);
}

// round 3
// speedup vs baseline: 1.4236x; 1.4236x over previous
#include <cuda_runtime.h>

// FastPooling "social" pooling, restructured:
//   H[j][cc][o] = sum_h hidden[j][h] * W[h*16+cc][o]        (dense GEMM, fp32)
//   out[i]      = relu(b + sum over winning fine cells c of H[winner(c)][coarse(c)])
// winner(c) = max j (last-write-wins == max-j); out-of-range peds "write zeros
// to cell 0" in the reference -> in_range bit in the encoded key so an
// out-of-range max-j suppresses cell 0's contribution.

#define N_MAX   512
#define HID     128
#define GRID_S  32
#define NCELLS  (GRID_S * GRID_S)   // 1024
#define CC_N    16                  // 4x4 coarse cells
#define OUTD    128

__device__ float g_H[N_MAX * CC_N * OUTD];   // 4 MB scratch

// ---------------------------------------------------------------------------
// K1: H = hidden (n x 128) @ Wperm, Wperm[k][cc*128+o] = W[(k*16+cc)*128+o]
// Tile: 64 rows x 128 cols per block; grid = (n/64, 16cc) = 128 blocks.
// ---------------------------------------------------------------------------
__global__ __launch_bounds__(256) void gemm1_kernel(
    const float* __restrict__ hidden,
    const float* __restrict__ W,
    int n)
{
    __shared__ __align__(16) float sh[64][HID];   // 32 KB hidden tile

    const int cc    = blockIdx.y;
    const int jbase = blockIdx.x * 64;
    const int t     = threadIdx.x;

    const float4* hsrc = reinterpret_cast<const float4*>(hidden + (size_t)jbase * HID);
    float4*       hdst = reinterpret_cast<float4*>(&sh[0][0]);
    #pragma unroll
    for (int idx = t; idx < 64 * HID / 4; idx += 256) hdst[idx] = hsrc[idx];
    __syncthreads();

    const int colg = (t & 31) * 4;     // 4 contiguous output cols
    const int rowg = (t >> 5) * 8;     // 8 rows

    float acc[8][4];
    #pragma unroll
    for (int r = 0; r < 8; ++r)
        #pragma unroll
        for (int q = 0; q < 4; ++q) acc[r][q] = 0.f;

    #pragma unroll 4
    for (int k = 0; k < HID; ++k) {
        const float4 w = *reinterpret_cast<const float4*>(
            W + ((size_t)(k * CC_N + cc)) * OUTD + colg);
        #pragma unroll
        for (int r = 0; r < 8; ++r) {
            const float a = sh[rowg + r][k];
            acc[r][0] += a * w.x;
            acc[r][1] += a * w.y;
            acc[r][2] += a * w.z;
            acc[r][3] += a * w.w;
        }
    }

    #pragma unroll
    for (int r = 0; r < 8; ++r) {
        const int j = jbase + rowg + r;
        if (j < n) {
            float4 v = make_float4(acc[r][0], acc[r][1], acc[r][2], acc[r][3]);
            *reinterpret_cast<float4*>(g_H + ((size_t)j * CC_N + cc) * OUTD + colg) = v;
        }
    }
}

// ---------------------------------------------------------------------------
// K2: per ped i — winner scatter (shared atomicMax), compact valid winners,
// then branch-free 4-way-unrolled gather-sum of H rows (MLP >= 4).
// ---------------------------------------------------------------------------
__global__ __launch_bounds__(256) void pool_gather_kernel(
    const float* __restrict__ obs2,
    const float* __restrict__ bias,
    float* __restrict__ out,
    int n)
{
    __shared__ __align__(16) float red[8][OUTD];  // per-warp partial sums (float4 access)
    __shared__ int   win[NCELLS];     // encoded (j<<1)|in_range, -1 = empty
    __shared__ int   lst[NCELLS];     // compacted j*16+cc
    __shared__ int   cnt;

    const int i    = blockIdx.x;
    const int t    = threadIdx.x;
    const int w    = t >> 5;
    const int lane = t & 31;

    if (t == 0) cnt = 0;
    for (int c = t; c < NCELLS; c += 256) win[c] = -1;
    __syncthreads();

    const float xi = obs2[i * 2 + 0];
    const float yi = obs2[i * 2 + 1];

    // scatter: last-write-wins == max j
    for (int j = t; j < n; j += 256) {
        if (j == i) continue;
        const float ox = (obs2[j * 2 + 0] - xi) * 4.0f + 16.0f;
        const float oy = (obs2[j * 2 + 1] - yi) * 4.0f + 16.0f;
        const bool inr = (ox >= 0.f) & (ox < 32.f) & (oy >= 0.f) & (oy < 32.f);
        int cell = 0;
        if (inr) cell = ((int)ox) * GRID_S + (int)oy;
        atomicMax(&win[cell], (j << 1) | (inr ? 1 : 0));
    }
    __syncthreads();

    // compact valid (in-range) winners: warp-aggregated append
    #pragma unroll
    for (int base_c = 0; base_c < NCELLS; base_c += 256) {
        const int c   = base_c + t;
        const int enc = win[c];
        const bool valid = (enc >= 0) && (enc & 1);
        const unsigned mask = __ballot_sync(0xffffffffu, valid);
        if (mask) {
            const int leader = __ffs(mask) - 1;
            int base = 0;
            if (lane == leader) base = atomicAdd(&cnt, __popc(mask));
            base = __shfl_sync(0xffffffffu, base, leader);
            if (valid) {
                const int j  = enc >> 1;
                const int cc = (c >> 8) * 4 + ((c >> 3) & 3);
                lst[base + __popc(mask & ((1u << lane) - 1u))] = j * CC_N + cc;
            }
        }
    }
    __syncthreads();
    const int m = cnt;

    // gather: warps stride the compact list; 4-way unroll -> 4 LDG.128 in flight
    float4 acc0 = make_float4(0.f, 0.f, 0.f, 0.f);
    float4 acc1 = make_float4(0.f, 0.f, 0.f, 0.f);
    const int co = lane * 4;

    int e = w;
    for (; e + 24 < m; e += 32) {
        const int p0 = lst[e];
        const int p1 = lst[e + 8];
        const int p2 = lst[e + 16];
        const int p3 = lst[e + 24];
        const float4 v0 = *reinterpret_cast<const float4*>(g_H + (size_t)p0 * OUTD + co);
        const float4 v1 = *reinterpret_cast<const float4*>(g_H + (size_t)p1 * OUTD + co);
        const float4 v2 = *reinterpret_cast<const float4*>(g_H + (size_t)p2 * OUTD + co);
        const float4 v3 = *reinterpret_cast<const float4*>(g_H + (size_t)p3 * OUTD + co);
        acc0.x += v0.x; acc0.y += v0.y; acc0.z += v0.z; acc0.w += v0.w;
        acc1.x += v1.x; acc1.y += v1.y; acc1.z += v1.z; acc1.w += v1.w;
        acc0.x += v2.x; acc0.y += v2.y; acc0.z += v2.z; acc0.w += v2.w;
        acc1.x += v3.x; acc1.y += v3.y; acc1.z += v3.z; acc1.w += v3.w;
    }
    for (; e < m; e += 8) {
        const int p = lst[e];
        const float4 v = *reinterpret_cast<const float4*>(g_H + (size_t)p * OUTD + co);
        acc0.x += v.x; acc0.y += v.y; acc0.z += v.z; acc0.w += v.w;
    }
    acc0.x += acc1.x; acc0.y += acc1.y; acc0.z += acc1.z; acc0.w += acc1.w;

    *reinterpret_cast<float4*>(&red[w][co]) = acc0;
    __syncthreads();

    if (t < OUTD) {
        float s = bias[t];
        #pragma unroll
        for (int r = 0; r < 8; ++r) s += red[r][t];
        out[(size_t)i * OUTD + t] = fmaxf(s, 0.f);
    }
}

// ---------------------------------------------------------------------------
// inputs: hidden_state (n,128) f32 | obs1 (n,2) f32 (unused) | obs2 (n,2) f32 |
//         W (2048,128) f32 | b (128,) f32   -> out (n,128) f32
// ---------------------------------------------------------------------------
extern "C" void kernel_launch(void* const* d_in, const int* in_sizes, int n_in,
                              void* d_out, int out_size)
{
    const float* hidden = (const float*)d_in[0];
    const float* obs2   = (const float*)d_in[2];
    const float* W      = (const float*)d_in[3];
    const float* bias   = (const float*)d_in[4];
    float*       out    = (float*)d_out;

    const int n = in_sizes[2] / 2;   // 512

    dim3 g1((n + 63) / 64, CC_N);
    gemm1_kernel<<<g1, 256>>>(hidden, W, n);
    pool_gather_kernel<<<n, 256>>>(obs2, bias, out, n);
}

// round 4
// speedup vs baseline: 1.8779x; 1.3191x over previous
#include <cuda_runtime.h>

// FastPooling "social": H[j][cc][:] = hidden[j] @ W[:,cc,:]; out[i] = relu(b +
// sum over winning fine cells of H[winner][coarse]). winner = max-j (last-write
// -wins); out-of-range peds write zeros to cell 0 -> in_range bit suppresses.

#define N_MAX   512
#define HID     128
#define GRID_S  32
#define NCELLS  (GRID_S * GRID_S)   // 1024
#define CC_N    16
#define OUTD    128

__device__ float g_H[N_MAX * CC_N * OUTD];   // 4 MB scratch

// ---------------------------------------------------------------------------
// K1: H = hidden (n x 128) @ Wperm. Tile 32 rows x 128 cols, one cc per block.
// W double-buffered through shared (chunks of 16 k). Grid (n/32, 16) = 256.
// ---------------------------------------------------------------------------
__global__ __launch_bounds__(256) void gemm1_kernel(
    const float* __restrict__ hidden,
    const float* __restrict__ W,
    int n)
{
    __shared__ __align__(16) float sh[32][HID];        // 16 KB A tile
    __shared__ __align__(16) float sW[2][16][OUTD];    // 2 x 8 KB W chunks

    const int cc    = blockIdx.y;
    const int jbase = blockIdx.x * 32;
    const int t     = threadIdx.x;

    // A tile load (coalesced float4): 32*32 float4 / 256 thr = 4 each
    {
        const float4* hsrc = reinterpret_cast<const float4*>(hidden + (size_t)jbase * HID);
        float4*       hdst = reinterpret_cast<float4*>(&sh[0][0]);
        #pragma unroll
        for (int s = 0; s < 4; ++s) hdst[t + 256 * s] = hsrc[t + 256 * s];
    }

    // W chunk addressing: chunk c covers k = c*16 .. c*16+15
    const int kl   = t >> 5;          // k_local 0..7  (x2 via s)
    const int col4 = t & 31;          // float4 column
    const float4* Wv = reinterpret_cast<const float4*>(W);
    // float4 index of W[(k*16+cc)*128 + col4*4] = ((k*16+cc)*128)/4 + col4
    #define WIDX(k) ((size_t)(((k) * CC_N + cc)) * (OUTD / 4) + col4)

    float4 r0 = Wv[WIDX(kl)];
    float4 r1 = Wv[WIDX(kl + 8)];
    *reinterpret_cast<float4*>(&sW[0][kl][col4 * 4])     = r0;
    *reinterpret_cast<float4*>(&sW[0][kl + 8][col4 * 4]) = r1;
    __syncthreads();

    const int colg = (t & 31) * 4;
    const int rowg = (t >> 5) * 4;

    float acc[4][4];
    #pragma unroll
    for (int r = 0; r < 4; ++r)
        #pragma unroll
        for (int q = 0; q < 4; ++q) acc[r][q] = 0.f;

    #pragma unroll
    for (int c = 0; c < 8; ++c) {
        const int buf = c & 1;
        if (c < 7) {                          // prefetch next chunk (LDG in flight)
            r0 = Wv[WIDX((c + 1) * 16 + kl)];
            r1 = Wv[WIDX((c + 1) * 16 + kl + 8)];
        }
        #pragma unroll
        for (int kk = 0; kk < 16; ++kk) {
            const int k = c * 16 + kk;
            const float4 w = *reinterpret_cast<const float4*>(&sW[buf][kk][colg]);
            const float a0 = sh[rowg + 0][k];
            const float a1 = sh[rowg + 1][k];
            const float a2 = sh[rowg + 2][k];
            const float a3 = sh[rowg + 3][k];
            acc[0][0] += a0 * w.x; acc[0][1] += a0 * w.y; acc[0][2] += a0 * w.z; acc[0][3] += a0 * w.w;
            acc[1][0] += a1 * w.x; acc[1][1] += a1 * w.y; acc[1][2] += a1 * w.z; acc[1][3] += a1 * w.w;
            acc[2][0] += a2 * w.x; acc[2][1] += a2 * w.y; acc[2][2] += a2 * w.z; acc[2][3] += a2 * w.w;
            acc[3][0] += a3 * w.x; acc[3][1] += a3 * w.y; acc[3][2] += a3 * w.z; acc[3][3] += a3 * w.w;
        }
        if (c < 7) {
            *reinterpret_cast<float4*>(&sW[buf ^ 1][kl][col4 * 4])     = r0;
            *reinterpret_cast<float4*>(&sW[buf ^ 1][kl + 8][col4 * 4]) = r1;
        }
        __syncthreads();
    }
    #undef WIDX

    #pragma unroll
    for (int r = 0; r < 4; ++r) {
        const int j = jbase + rowg + r;
        if (j < n) {
            float4 v = make_float4(acc[r][0], acc[r][1], acc[r][2], acc[r][3]);
            *reinterpret_cast<float4*>(g_H + ((size_t)j * CC_N + cc) * OUTD + colg) = v;
        }
    }
}

// ---------------------------------------------------------------------------
// K2: per ped i — winner scatter (shared atomicMax), compact, then 8-way
// unrolled branch-free gather-sum of H rows (MLP 8).
// ---------------------------------------------------------------------------
__global__ __launch_bounds__(256) void pool_gather_kernel(
    const float* __restrict__ obs2,
    const float* __restrict__ bias,
    float* __restrict__ out,
    int n)
{
    __shared__ __align__(16) float red[8][OUTD];
    __shared__ int   win[NCELLS];
    __shared__ int   lst[NCELLS];
    __shared__ int   cnt;

    const int i    = blockIdx.x;
    const int t    = threadIdx.x;
    const int w    = t >> 5;
    const int lane = t & 31;

    if (t == 0) cnt = 0;
    for (int c = t; c < NCELLS; c += 256) win[c] = -1;
    __syncthreads();

    const float xi = obs2[i * 2 + 0];
    const float yi = obs2[i * 2 + 1];

    for (int j = t; j < n; j += 256) {
        if (j == i) continue;
        const float ox = (obs2[j * 2 + 0] - xi) * 4.0f + 16.0f;
        const float oy = (obs2[j * 2 + 1] - yi) * 4.0f + 16.0f;
        const bool inr = (ox >= 0.f) & (ox < 32.f) & (oy >= 0.f) & (oy < 32.f);
        int cell = 0;
        if (inr) cell = ((int)ox) * GRID_S + (int)oy;
        atomicMax(&win[cell], (j << 1) | (inr ? 1 : 0));
    }
    __syncthreads();

    #pragma unroll
    for (int base_c = 0; base_c < NCELLS; base_c += 256) {
        const int c   = base_c + t;
        const int enc = win[c];
        const bool valid = (enc >= 0) && (enc & 1);
        const unsigned mask = __ballot_sync(0xffffffffu, valid);
        if (mask) {
            const int leader = __ffs(mask) - 1;
            int base = 0;
            if (lane == leader) base = atomicAdd(&cnt, __popc(mask));
            base = __shfl_sync(0xffffffffu, base, leader);
            if (valid) {
                const int j  = enc >> 1;
                const int cc = (c >> 8) * 4 + ((c >> 3) & 3);
                lst[base + __popc(mask & ((1u << lane) - 1u))] = j * CC_N + cc;
            }
        }
    }
    __syncthreads();
    const int m = cnt;

    float4 acc0 = make_float4(0.f, 0.f, 0.f, 0.f);
    float4 acc1 = make_float4(0.f, 0.f, 0.f, 0.f);
    const int co = lane * 4;

    int e = w;
    for (; e + 56 < m; e += 64) {     // 8 LDG.128 in flight
        const int p0 = lst[e];      const int p1 = lst[e + 8];
        const int p2 = lst[e + 16]; const int p3 = lst[e + 24];
        const int p4 = lst[e + 32]; const int p5 = lst[e + 40];
        const int p6 = lst[e + 48]; const int p7 = lst[e + 56];
        const float4 v0 = *reinterpret_cast<const float4*>(g_H + (size_t)p0 * OUTD + co);
        const float4 v1 = *reinterpret_cast<const float4*>(g_H + (size_t)p1 * OUTD + co);
        const float4 v2 = *reinterpret_cast<const float4*>(g_H + (size_t)p2 * OUTD + co);
        const float4 v3 = *reinterpret_cast<const float4*>(g_H + (size_t)p3 * OUTD + co);
        const float4 v4 = *reinterpret_cast<const float4*>(g_H + (size_t)p4 * OUTD + co);
        const float4 v5 = *reinterpret_cast<const float4*>(g_H + (size_t)p5 * OUTD + co);
        const float4 v6 = *reinterpret_cast<const float4*>(g_H + (size_t)p6 * OUTD + co);
        const float4 v7 = *reinterpret_cast<const float4*>(g_H + (size_t)p7 * OUTD + co);
        acc0.x += v0.x; acc0.y += v0.y; acc0.z += v0.z; acc0.w += v0.w;
        acc1.x += v1.x; acc1.y += v1.y; acc1.z += v1.z; acc1.w += v1.w;
        acc0.x += v2.x; acc0.y += v2.y; acc0.z += v2.z; acc0.w += v2.w;
        acc1.x += v3.x; acc1.y += v3.y; acc1.z += v3.z; acc1.w += v3.w;
        acc0.x += v4.x; acc0.y += v4.y; acc0.z += v4.z; acc0.w += v4.w;
        acc1.x += v5.x; acc1.y += v5.y; acc1.z += v5.z; acc1.w += v5.w;
        acc0.x += v6.x; acc0.y += v6.y; acc0.z += v6.z; acc0.w += v6.w;
        acc1.x += v7.x; acc1.y += v7.y; acc1.z += v7.z; acc1.w += v7.w;
    }
    for (; e + 24 < m; e += 32) {     // 4-way tail
        const int p0 = lst[e];      const int p1 = lst[e + 8];
        const int p2 = lst[e + 16]; const int p3 = lst[e + 24];
        const float4 v0 = *reinterpret_cast<const float4*>(g_H + (size_t)p0 * OUTD + co);
        const float4 v1 = *reinterpret_cast<const float4*>(g_H + (size_t)p1 * OUTD + co);
        const float4 v2 = *reinterpret_cast<const float4*>(g_H + (size_t)p2 * OUTD + co);
        const float4 v3 = *reinterpret_cast<const float4*>(g_H + (size_t)p3 * OUTD + co);
        acc0.x += v0.x; acc0.y += v0.y; acc0.z += v0.z; acc0.w += v0.w;
        acc1.x += v1.x; acc1.y += v1.y; acc1.z += v1.z; acc1.w += v1.w;
        acc0.x += v2.x; acc0.y += v2.y; acc0.z += v2.z; acc0.w += v2.w;
        acc1.x += v3.x; acc1.y += v3.y; acc1.z += v3.z; acc1.w += v3.w;
    }
    for (; e < m; e += 8) {
        const int p = lst[e];
        const float4 v = *reinterpret_cast<const float4*>(g_H + (size_t)p * OUTD + co);
        acc0.x += v.x; acc0.y += v.y; acc0.z += v.z; acc0.w += v.w;
    }
    acc0.x += acc1.x; acc0.y += acc1.y; acc0.z += acc1.z; acc0.w += acc1.w;

    *reinterpret_cast<float4*>(&red[w][co]) = acc0;
    __syncthreads();

    if (t < OUTD) {
        float s = bias[t];
        #pragma unroll
        for (int r = 0; r < 8; ++r) s += red[r][t];
        out[(size_t)i * OUTD + t] = fmaxf(s, 0.f);
    }
}

// ---------------------------------------------------------------------------
// inputs: hidden_state (n,128) f32 | obs1 (n,2) (unused) | obs2 (n,2) f32 |
//         W (2048,128) f32 | b (128,) f32   -> out (n,128) f32
// ---------------------------------------------------------------------------
extern "C" void kernel_launch(void* const* d_in, const int* in_sizes, int n_in,
                              void* d_out, int out_size)
{
    const float* hidden = (const float*)d_in[0];
    const float* obs2   = (const float*)d_in[2];
    const float* W      = (const float*)d_in[3];
    const float* bias   = (const float*)d_in[4];
    float*       out    = (float*)d_out;

    const int n = in_sizes[2] / 2;   // 512

    dim3 g1((n + 31) / 32, CC_N);
    gemm1_kernel<<<g1, 256>>>(hidden, W, n);
    pool_gather_kernel<<<n, 256>>>(obs2, bias, out, n);
}

// round 5
// speedup vs baseline: 2.0847x; 1.1102x over previous
#include <cuda_runtime.h>
#include <cuda_fp16.h>

// FastPooling "social": H[j][cc][:] = hidden[j] @ W[:,cc,:] (fp32 compute,
// fp16 store); out[i] = relu(b + sum over winning fine cells of
// H[winner][coarse]). winner = max-j (last-write-wins); out-of-range peds
// write zeros to cell 0 -> in_range bit suppresses cell 0.

#define N_MAX   512
#define HID     128
#define GRID_S  32
#define NCELLS  (GRID_S * GRID_S)   // 1024
#define CC_N    16
#define OUTD    128

typedef unsigned long long u64;

__device__ __half g_Hh[N_MAX * CC_N * OUTD];   // 2 MB scratch (fp16)

__device__ __forceinline__ u64 pack2(float lo, float hi) {
    u64 r; asm("mov.b64 %0, {%1, %2};" : "=l"(r) : "f"(lo), "f"(hi)); return r;
}
__device__ __forceinline__ void unpack2(float& lo, float& hi, u64 v) {
    asm("mov.b64 {%0, %1}, %2;" : "=f"(lo), "=f"(hi) : "l"(v));
}
__device__ __forceinline__ void fma2(u64& d, u64 a, u64 b) {
    asm("fma.rn.f32x2 %0, %1, %2, %0;" : "+l"(d) : "l"(a), "l"(b));
}

// ---------------------------------------------------------------------------
// K1: H = hidden (n x 128) @ Wperm, one cc per block, 64 rows x 128 cols.
// Thread tile 8 rows x 4 cols, FFMA2 inner, A via float4 k-broadcasts,
// W double-buffered in shared. Grid (n/64, 16) = 128 blocks.
// ---------------------------------------------------------------------------
__global__ __launch_bounds__(256) void gemm1_kernel(
    const float* __restrict__ hidden,
    const float* __restrict__ W,
    int n)
{
    __shared__ __align__(16) float sh[64][HID];        // 32 KB A tile
    __shared__ __align__(16) float sW[2][16][OUTD];    // 2 x 8 KB W chunks

    const int cc    = blockIdx.y;
    const int jbase = blockIdx.x * 64;
    const int t     = threadIdx.x;

    // A tile: 64*32 float4 / 256 thr = 8 each
    {
        const float4* hsrc = reinterpret_cast<const float4*>(hidden + (size_t)jbase * HID);
        float4*       hdst = reinterpret_cast<float4*>(&sh[0][0]);
        #pragma unroll
        for (int s = 0; s < 8; ++s) {
            const int idx = t + 256 * s;
            if (jbase + (idx >> 5) < n) hdst[idx] = hsrc[idx];
        }
    }

    const int kl   = t >> 5;          // 0..7
    const int col4 = t & 31;
    const float4* Wv = reinterpret_cast<const float4*>(W);
    #define WIDX(k) ((size_t)(((k) * CC_N + cc)) * (OUTD / 4) + col4)

    float4 r0 = Wv[WIDX(kl)];
    float4 r1 = Wv[WIDX(kl + 8)];
    *reinterpret_cast<float4*>(&sW[0][kl][col4 * 4])     = r0;
    *reinterpret_cast<float4*>(&sW[0][kl + 8][col4 * 4]) = r1;
    __syncthreads();

    const int colg = (t & 31) * 4;     // 4 output cols
    const int rowg = (t >> 5) * 8;     // 8 rows

    u64 acc[8][2];
    #pragma unroll
    for (int r = 0; r < 8; ++r) { acc[r][0] = 0ull; acc[r][1] = 0ull; }

    #pragma unroll
    for (int c = 0; c < 8; ++c) {
        const int buf = c & 1;
        if (c < 7) {
            r0 = Wv[WIDX((c + 1) * 16 + kl)];
            r1 = Wv[WIDX((c + 1) * 16 + kl + 8)];
        }
        #pragma unroll
        for (int kk = 0; kk < 16; kk += 4) {
            // W for 4 k's: each longlong2 = (w[c0],w[c1]),(w[c2],w[c3]) packed
            longlong2 wv0 = *reinterpret_cast<const longlong2*>(&sW[buf][kk + 0][colg]);
            longlong2 wv1 = *reinterpret_cast<const longlong2*>(&sW[buf][kk + 1][colg]);
            longlong2 wv2 = *reinterpret_cast<const longlong2*>(&sW[buf][kk + 2][colg]);
            longlong2 wv3 = *reinterpret_cast<const longlong2*>(&sW[buf][kk + 3][colg]);
            const int k0 = c * 16 + kk;
            #pragma unroll
            for (int r = 0; r < 8; ++r) {
                const float4 av = *reinterpret_cast<const float4*>(&sh[rowg + r][k0]); // warp-uniform broadcast
                u64 a0 = pack2(av.x, av.x);
                u64 a1 = pack2(av.y, av.y);
                u64 a2 = pack2(av.z, av.z);
                u64 a3 = pack2(av.w, av.w);
                fma2(acc[r][0], a0, (u64)wv0.x); fma2(acc[r][1], a0, (u64)wv0.y);
                fma2(acc[r][0], a1, (u64)wv1.x); fma2(acc[r][1], a1, (u64)wv1.y);
                fma2(acc[r][0], a2, (u64)wv2.x); fma2(acc[r][1], a2, (u64)wv2.y);
                fma2(acc[r][0], a3, (u64)wv3.x); fma2(acc[r][1], a3, (u64)wv3.y);
            }
        }
        if (c < 7) {
            *reinterpret_cast<float4*>(&sW[buf ^ 1][kl][col4 * 4])     = r0;
            *reinterpret_cast<float4*>(&sW[buf ^ 1][kl + 8][col4 * 4]) = r1;
        }
        __syncthreads();
    }
    #undef WIDX

    #pragma unroll
    for (int r = 0; r < 8; ++r) {
        const int j = jbase + rowg + r;
        if (j < n) {
            float v0, v1, v2, v3;
            unpack2(v0, v1, acc[r][0]);
            unpack2(v2, v3, acc[r][1]);
            __half2 h0 = __floats2half2_rn(v0, v1);
            __half2 h1 = __floats2half2_rn(v2, v3);
            uint2 st;
            st.x = *reinterpret_cast<unsigned*>(&h0);
            st.y = *reinterpret_cast<unsigned*>(&h1);
            *reinterpret_cast<uint2*>(g_Hh + ((size_t)j * CC_N + cc) * OUTD + colg) = st;
        }
    }
}

// ---------------------------------------------------------------------------
// K2: per ped i — winner scatter (shared atomicMax), compact, then 8-way
// unrolled branch-free gather-sum of fp16 H rows (uint2 per lane).
// ---------------------------------------------------------------------------
__global__ __launch_bounds__(256) void pool_gather_kernel(
    const float* __restrict__ obs2,
    const float* __restrict__ bias,
    float* __restrict__ out,
    int n)
{
    __shared__ __align__(16) float red[8][OUTD];
    __shared__ int   win[NCELLS];
    __shared__ int   lst[NCELLS];
    __shared__ int   cnt;

    const int i    = blockIdx.x;
    const int t    = threadIdx.x;
    const int w    = t >> 5;
    const int lane = t & 31;

    if (t == 0) cnt = 0;
    for (int c = t; c < NCELLS; c += 256) win[c] = -1;
    __syncthreads();

    const float xi = obs2[i * 2 + 0];
    const float yi = obs2[i * 2 + 1];

    for (int j = t; j < n; j += 256) {
        if (j == i) continue;
        const float ox = (obs2[j * 2 + 0] - xi) * 4.0f + 16.0f;
        const float oy = (obs2[j * 2 + 1] - yi) * 4.0f + 16.0f;
        const bool inr = (ox >= 0.f) & (ox < 32.f) & (oy >= 0.f) & (oy < 32.f);
        int cell = 0;
        if (inr) cell = ((int)ox) * GRID_S + (int)oy;
        atomicMax(&win[cell], (j << 1) | (inr ? 1 : 0));
    }
    __syncthreads();

    #pragma unroll
    for (int base_c = 0; base_c < NCELLS; base_c += 256) {
        const int c   = base_c + t;
        const int enc = win[c];
        const bool valid = (enc >= 0) && (enc & 1);
        const unsigned mask = __ballot_sync(0xffffffffu, valid);
        if (mask) {
            const int leader = __ffs(mask) - 1;
            int base = 0;
            if (lane == leader) base = atomicAdd(&cnt, __popc(mask));
            base = __shfl_sync(0xffffffffu, base, leader);
            if (valid) {
                const int j  = enc >> 1;
                const int cc = (c >> 8) * 4 + ((c >> 3) & 3);
                lst[base + __popc(mask & ((1u << lane) - 1u))] = j * CC_N + cc;
            }
        }
    }
    __syncthreads();
    const int m = cnt;

    float4 acc0 = make_float4(0.f, 0.f, 0.f, 0.f);
    float4 acc1 = make_float4(0.f, 0.f, 0.f, 0.f);
    const int co = lane * 4;           // 4 halfs per lane

    #define ACCUM(A, u) do {                                              \
        const __half2 _h0 = *reinterpret_cast<const __half2*>(&(u).x);    \
        const __half2 _h1 = *reinterpret_cast<const __half2*>(&(u).y);    \
        const float2 _f0 = __half22float2(_h0);                           \
        const float2 _f1 = __half22float2(_h1);                           \
        A.x += _f0.x; A.y += _f0.y; A.z += _f1.x; A.w += _f1.y;           \
    } while (0)

    int e = w;
    for (; e + 56 < m; e += 64) {
        const int p0 = lst[e];      const int p1 = lst[e + 8];
        const int p2 = lst[e + 16]; const int p3 = lst[e + 24];
        const int p4 = lst[e + 32]; const int p5 = lst[e + 40];
        const int p6 = lst[e + 48]; const int p7 = lst[e + 56];
        const uint2 v0 = *reinterpret_cast<const uint2*>(g_Hh + (size_t)p0 * OUTD + co);
        const uint2 v1 = *reinterpret_cast<const uint2*>(g_Hh + (size_t)p1 * OUTD + co);
        const uint2 v2 = *reinterpret_cast<const uint2*>(g_Hh + (size_t)p2 * OUTD + co);
        const uint2 v3 = *reinterpret_cast<const uint2*>(g_Hh + (size_t)p3 * OUTD + co);
        const uint2 v4 = *reinterpret_cast<const uint2*>(g_Hh + (size_t)p4 * OUTD + co);
        const uint2 v5 = *reinterpret_cast<const uint2*>(g_Hh + (size_t)p5 * OUTD + co);
        const uint2 v6 = *reinterpret_cast<const uint2*>(g_Hh + (size_t)p6 * OUTD + co);
        const uint2 v7 = *reinterpret_cast<const uint2*>(g_Hh + (size_t)p7 * OUTD + co);
        ACCUM(acc0, v0); ACCUM(acc1, v1); ACCUM(acc0, v2); ACCUM(acc1, v3);
        ACCUM(acc0, v4); ACCUM(acc1, v5); ACCUM(acc0, v6); ACCUM(acc1, v7);
    }
    for (; e + 24 < m; e += 32) {
        const int p0 = lst[e];      const int p1 = lst[e + 8];
        const int p2 = lst[e + 16]; const int p3 = lst[e + 24];
        const uint2 v0 = *reinterpret_cast<const uint2*>(g_Hh + (size_t)p0 * OUTD + co);
        const uint2 v1 = *reinterpret_cast<const uint2*>(g_Hh + (size_t)p1 * OUTD + co);
        const uint2 v2 = *reinterpret_cast<const uint2*>(g_Hh + (size_t)p2 * OUTD + co);
        const uint2 v3 = *reinterpret_cast<const uint2*>(g_Hh + (size_t)p3 * OUTD + co);
        ACCUM(acc0, v0); ACCUM(acc1, v1); ACCUM(acc0, v2); ACCUM(acc1, v3);
    }
    for (; e < m; e += 8) {
        const int p = lst[e];
        const uint2 v = *reinterpret_cast<const uint2*>(g_Hh + (size_t)p * OUTD + co);
        ACCUM(acc0, v);
    }
    #undef ACCUM
    acc0.x += acc1.x; acc0.y += acc1.y; acc0.z += acc1.z; acc0.w += acc1.w;

    *reinterpret_cast<float4*>(&red[w][co]) = acc0;
    __syncthreads();

    if (t < OUTD) {
        float s = bias[t];
        #pragma unroll
        for (int r = 0; r < 8; ++r) s += red[r][t];
        out[(size_t)i * OUTD + t] = fmaxf(s, 0.f);
    }
}

// ---------------------------------------------------------------------------
// inputs: hidden_state (n,128) f32 | obs1 (n,2) (unused) | obs2 (n,2) f32 |
//         W (2048,128) f32 | b (128,) f32   -> out (n,128) f32
// ---------------------------------------------------------------------------
extern "C" void kernel_launch(void* const* d_in, const int* in_sizes, int n_in,
                              void* d_out, int out_size)
{
    const float* hidden = (const float*)d_in[0];
    const float* obs2   = (const float*)d_in[2];
    const float* W      = (const float*)d_in[3];
    const float* bias   = (const float*)d_in[4];
    float*       out    = (float*)d_out;

    const int n = in_sizes[2] / 2;   // 512

    dim3 g1((n + 63) / 64, CC_N);
    gemm1_kernel<<<g1, 256>>>(hidden, W, n);
    pool_gather_kernel<<<n, 256>>>(obs2, bias, out, n);
}